// round 15
// baseline (speedup 1.0000x reference)
#include <cuda_runtime.h>
#include <cuda_fp16.h>
#include <cstdint>

#define T_DIM 2048
#define H_DIM 4096
#define O_DIM 4096
#define L_DIM 32
#define R_DIM 16

#define BM 128
#define BN 64
#define BK 32
#define KT_N (H_DIM / BK)          // 128 k-tiles
#define STAGES 4
#define MAT_A_BYTES 8192           // 128 rows x 64 bytes
#define MAT_B_BYTES 4096           // 64 rows x 64 bytes
#define STAGE_BYTES (MAT_A_BYTES + MAT_B_BYTES)   // 12 KB
#define DYN_SMEM (STAGES * STAGE_BYTES)           // 48 KB

#define SH_CH 8                    // shrink H-chunks
#define SH_Z 8                     // shrink token-split
#define CHUNK4 (H_DIM / 4 / SH_CH) // 128 float4 per chunk
#define FX_Z 8                     // fixup token-split
#define FX_CHUNK 32                // staged tokens per round

// ---------------- device scratch ----------------
__device__ int    g_idx32[T_DIM];
__device__ int    g_tok[T_DIM];
__device__ int    g_cnt[L_DIM];
__device__ int    g_base[L_DIM];
__device__ float  g_shrunk[T_DIM * R_DIM];
__device__ __half g_Xhi[T_DIM * H_DIM];
__device__ __half g_Whi[O_DIM * H_DIM];

// ---------------- helpers ----------------
__device__ __forceinline__ uint32_t smem_u32(const void* p) {
    uint32_t a;
    asm("{ .reg .u64 t; cvta.to.shared.u64 t, %1; cvt.u32.u64 %0, t; }"
        : "=r"(a) : "l"(p));
    return a;
}

__device__ __forceinline__ uint32_t swz(uint32_t o) {
    return o ^ ((o >> 3) & 0x30);   // 64B-row swizzle
}

#define CP_ASYNC16(dst, src) \
    asm volatile("cp.async.cg.shared.global [%0], [%1], 16;" :: "r"(dst), "l"(src))
#define CP_COMMIT() asm volatile("cp.async.commit_group;" ::: "memory")
#define CP_WAIT2()  asm volatile("cp.async.wait_group 2;" ::: "memory")

#define LDSM4(d0, d1, d2, d3, a)                                          \
    asm volatile("ldmatrix.sync.aligned.m8n8.x4.shared.b16 {%0,%1,%2,%3}, [%4];" \
                 : "=r"(d0), "=r"(d1), "=r"(d2), "=r"(d3) : "r"(a))

__device__ __forceinline__ void mma16816h(float* c, const uint32_t* a,
                                          uint32_t b0, uint32_t b1) {
    asm volatile(
        "mma.sync.aligned.m16n8k16.row.col.f32.f16.f16.f32 "
        "{%0,%1,%2,%3}, {%4,%5,%6,%7}, {%8,%9}, {%0,%1,%2,%3};"
        : "+f"(c[0]), "+f"(c[1]), "+f"(c[2]), "+f"(c[3])
        : "r"(a[0]), "r"(a[1]), "r"(a[2]), "r"(a[3]), "r"(b0), "r"(b1));
}

// ---------------------------------------------------------------------------
// Kernel 1: index decode (int64 vs int32) + bucket tokens + zero g_shrunk.
// ---------------------------------------------------------------------------
__global__ void bucket_kernel(const int* __restrict__ raw) {
    __shared__ int bad;
    __shared__ int s_cnt[L_DIM];
    __shared__ int s_base[L_DIM];
    const int tid = threadIdx.x;
    if (tid == 0) bad = 0;
    if (tid < L_DIM) s_cnt[tid] = 0;
    __syncthreads();
    {   // 256 pairs = 2048 bytes, in-bounds for either width
        int lo = raw[2 * tid], hi = raw[2 * tid + 1];
        bool ok = (hi == 0 && lo >= 0) || (hi == -1 && lo < 0);
        if (!ok) bad = 1;
    }
    __syncthreads();
    const bool is64 = (bad == 0);
    for (int t = tid; t < T_DIM; t += 256) {
        int v = is64 ? raw[2 * t] : raw[t];
        g_idx32[t] = v;
        if (v >= 0) atomicAdd(&s_cnt[v], 1);
    }
    for (int i = tid; i < T_DIM * R_DIM / 4; i += 256)
        ((float4*)g_shrunk)[i] = make_float4(0, 0, 0, 0);
    __syncthreads();
    if (tid == 0) {
        int a = 0;
        for (int l = 0; l < L_DIM; l++) { s_base[l] = a; a += s_cnt[l]; }
    }
    __syncthreads();
    if (tid < L_DIM) {
        g_cnt[tid] = s_cnt[tid];
        g_base[tid] = s_base[tid];
        s_cnt[tid] = 0;
    }
    __syncthreads();
    for (int t = tid; t < T_DIM; t += 256) {
        int v = g_idx32[t];
        if (v >= 0) {
            int p = atomicAdd(&s_cnt[v], 1);
            g_tok[s_base[v] + p] = t;
        }
    }
}

// ---------------------------------------------------------------------------
// Kernel 2a: fp32 -> fp16 of X
// ---------------------------------------------------------------------------
__global__ void convert_x(const float* __restrict__ src) {
    int i = blockIdx.x * blockDim.x + threadIdx.x;
    if (i >= T_DIM * H_DIM / 4) return;
    float4 v = ((const float4*)src)[i];
    uint2 ph;
    ph.x = ((uint32_t)__half_as_ushort(__float2half(v.y)) << 16) |
           __half_as_ushort(__float2half(v.x));
    ph.y = ((uint32_t)__half_as_ushort(__float2half(v.w)) << 16) |
           __half_as_ushort(__float2half(v.z));
    ((uint2*)g_Xhi)[i] = ph;
}

// ---------------------------------------------------------------------------
// Kernel 2b: fp32 -> fp16 of W, row-chunked (half of W per launch)
// ---------------------------------------------------------------------------
__global__ void convert_w(const float* __restrict__ src, int base4) {
    int i = base4 + blockIdx.x * blockDim.x + threadIdx.x;
    float4 v = ((const float4*)src)[i];
    uint2 ph;
    ph.x = ((uint32_t)__half_as_ushort(__float2half(v.y)) << 16) |
           __half_as_ushort(__float2half(v.x));
    ph.y = ((uint32_t)__half_as_ushort(__float2half(v.w)) << 16) |
           __half_as_ushort(__float2half(v.z));
    ((uint2*)g_Whi)[i] = ph;
}

// ---------------------------------------------------------------------------
// Kernel 3: LoRA shrink, grid (32 adapters, 8 H-chunks, 8 token-slices).
//   Runs CONCURRENTLY with the GEMM (only fixup consumes g_shrunk).
// ---------------------------------------------------------------------------
__global__ __launch_bounds__(256) void shrink3(
    const float* __restrict__ x, const float* __restrict__ lora_a) {
    __shared__ float4 sA4[R_DIM * CHUNK4];       // 16 x 128 float4 = 32 KB
    const int l = blockIdx.x;
    const int n = g_cnt[l];
    if (n == 0) return;
    const int tid = threadIdx.x;
    const int wid = tid >> 5, lid = tid & 31;
    const int slot = blockIdx.z * 8 + wid;       // 0..SH_Z*8-1
    if (blockIdx.z * 8 >= n) return;             // whole block idle -> skip
    const int hb4 = blockIdx.y * CHUNK4;

    const float4* a4 = ((const float4*)lora_a) + (size_t)l * R_DIM * (H_DIM / 4);
    for (int i = tid; i < R_DIM * CHUNK4; i += 256) {
        int r = i / CHUNK4, j4 = i % CHUNK4;
        sA4[i] = a4[r * (H_DIM / 4) + hb4 + j4];
    }
    __syncthreads();

    const int base = g_base[l];
    for (int ti = slot; ti < n; ti += SH_Z * 8) {
        const int t = g_tok[base + ti];
        const float4* x4 = ((const float4*)x) + (size_t)t * (H_DIM / 4) + hb4;
        float4 xv[4];
#pragma unroll
        for (int j = 0; j < 4; j++) xv[j] = x4[lid + 32 * j];
        float acc[R_DIM];
#pragma unroll
        for (int r = 0; r < R_DIM; r++) acc[r] = 0.0f;
#pragma unroll
        for (int j = 0; j < 4; j++) {
#pragma unroll
            for (int r = 0; r < R_DIM; r++) {
                float4 av = sA4[r * CHUNK4 + lid + 32 * j];
                acc[r] += xv[j].x * av.x + xv[j].y * av.y +
                          xv[j].z * av.z + xv[j].w * av.w;
            }
        }
#pragma unroll
        for (int r = 0; r < R_DIM; r++) {
            float v = acc[r];
#pragma unroll
            for (int off = 16; off > 0; off >>= 1)
                v += __shfl_down_sync(0xffffffff, v, off);
            if (lid == 0) atomicAdd(&g_shrunk[t * R_DIM + r], v);
        }
    }
}

// ---------------------------------------------------------------------------
// Kernel 4: fp16 HMMA GEMM (column-range half), epilogue = acc + bias.
//   128x64 tiles, 4-stage cp.async, occ 3. nbase = n-tile offset.
//   The two halves run CONCURRENTLY on different streams -> packing intact.
// ---------------------------------------------------------------------------
__global__ void __launch_bounds__(256, 3) gemm_hmma(
    const float* __restrict__ bias, float* __restrict__ out, int nbase) {
    extern __shared__ char dynsmem[];
    const uint32_t sbase = smem_u32(dynsmem);
    const int tid = threadIdx.x;
    const int wid = tid >> 5, lid = tid & 31;
    const int m0 = blockIdx.y * BM, n0 = (blockIdx.x + nbase) * BN;
    const int warp_m = wid & 3;        // 0..3 -> 32-row bands
    const int warp_n = wid >> 2;       // 0..1 -> 32-col bands

    const __half* gsrc[3];
    uint32_t sdst[3];
    {
        const __half* baseA = g_Xhi + (size_t)m0 * H_DIM;
        const __half* baseB = g_Whi + (size_t)n0 * H_DIM;
#pragma unroll
        for (int i = 0; i < 3; i++) {
            int c = tid + 256 * i;
            int mat = (c >= 512);
            int w = mat ? (c - 512) : c;
            int row = w >> 2, cq = w & 3;
            gsrc[i] = (mat ? baseB : baseA) + (size_t)row * H_DIM + cq * 8;
            sdst[i] = (mat ? MAT_A_BYTES : 0) + swz((uint32_t)(row * 64 + cq * 16));
        }
    }

#pragma unroll
    for (int s = 0; s < STAGES - 1; s++) {
        uint32_t sb = sbase + s * STAGE_BYTES;
#pragma unroll
        for (int i = 0; i < 3; i++) CP_ASYNC16(sb + sdst[i], gsrc[i] + s * BK);
        CP_COMMIT();
    }

    float acc[2][4][4];
#pragma unroll
    for (int a = 0; a < 2; a++)
#pragma unroll
        for (int b = 0; b < 4; b++)
#pragma unroll
            for (int c = 0; c < 4; c++) acc[a][b][c] = 0.0f;

    const uint32_t a_row = warp_m * 32 + (lid & 15);
    const uint32_t a_kb  = ((lid >> 4) & 1) * 16;
    const uint32_t b_row = warp_n * 32 + ((lid >> 4) & 1) * 8 + (lid & 7);
    const uint32_t b_kb  = ((lid >> 3) & 1) * 16;

#pragma unroll 1
    for (int kt = 0; kt < KT_N; kt++) {
        CP_WAIT2();
        __syncthreads();
        const int nt = kt + STAGES - 1;
        if (nt < KT_N) {
            uint32_t sb = sbase + (nt & 3) * STAGE_BYTES;
#pragma unroll
            for (int i = 0; i < 3; i++) CP_ASYNC16(sb + sdst[i], gsrc[i] + nt * BK);
        }
        CP_COMMIT();

        const uint32_t st = sbase + (kt & 3) * STAGE_BYTES;
#pragma unroll
        for (int kk = 0; kk < 2; kk++) {
            const uint32_t koff = kk * 32;
            uint32_t bh[2][4];
#pragma unroll
            for (int nj2 = 0; nj2 < 2; nj2++) {
                uint32_t o = swz((b_row + nj2 * 16) * 64 + koff + b_kb);
                LDSM4(bh[nj2][0], bh[nj2][1], bh[nj2][2], bh[nj2][3],
                      st + MAT_A_BYTES + o);
            }
#pragma unroll
            for (int mi = 0; mi < 2; mi++) {
                uint32_t ah[4];
                uint32_t o = swz((a_row + mi * 16) * 64 + koff + a_kb);
                LDSM4(ah[0], ah[1], ah[2], ah[3], st + o);
#pragma unroll
                for (int nj = 0; nj < 4; nj++) {
                    const uint32_t b0 = bh[nj >> 1][2 * (nj & 1)];
                    const uint32_t b1 = bh[nj >> 1][2 * (nj & 1) + 1];
                    mma16816h(acc[mi][nj], ah, b0, b1);
                }
            }
        }
    }

    // ---------------- epilogue: + bias only ----------------
    const int l4 = lid >> 2, lq = lid & 3;
    const int colbase = n0 + warp_n * 32 + 2 * lq;
    float2 bia[4];
#pragma unroll
    for (int ni = 0; ni < 4; ni++) {
        bia[ni].x = __ldg(bias + colbase + ni * 8);
        bia[ni].y = __ldg(bias + colbase + ni * 8 + 1);
    }
#pragma unroll
    for (int mi = 0; mi < 2; mi++) {
#pragma unroll
        for (int h = 0; h < 2; h++) {
            const int row = m0 + warp_m * 32 + mi * 16 + h * 8 + l4;
            float* orow = out + (size_t)row * O_DIM;
#pragma unroll
            for (int ni = 0; ni < 4; ni++) {
                const int col = colbase + ni * 8;
                *(float2*)(orow + col) =
                    make_float2(acc[mi][ni][h * 2 + 0] + bia[ni].x,
                                acc[mi][ni][h * 2 + 1] + bia[ni].y);
            }
        }
    }
}

// ---------------------------------------------------------------------------
// Kernel 5: LoRA fixup (post-GEMM): out[t, c] += shrunk[t,:] . B[l, c, :]
// ---------------------------------------------------------------------------
__global__ __launch_bounds__(256) void fixup_kernel(
    const float* __restrict__ lora_b, float* __restrict__ out) {
    __shared__ float4 sS[FX_CHUNK][4];
    __shared__ int    sT[FX_CHUNK];
    const int l = blockIdx.x;
    const int n = g_cnt[l];
    const int z = blockIdx.z;
    if (z >= n) return;
    const int c0 = blockIdx.y * 512 + threadIdx.x * 2;

    const float4* b0 = (const float4*)(lora_b + ((size_t)l * O_DIM + c0) * R_DIM);
    const float4* b1 = (const float4*)(lora_b + ((size_t)l * O_DIM + c0 + 1) * R_DIM);
    float4 B0[4], B1[4];
#pragma unroll
    for (int q = 0; q < 4; q++) { B0[q] = b0[q]; B1[q] = b1[q]; }

    const int base = g_base[l];
    for (int ck = z; ck < n; ck += FX_Z * FX_CHUNK) {
        int cnt = (n - ck + FX_Z - 1) / FX_Z;
        if (cnt > FX_CHUNK) cnt = FX_CHUNK;
        __syncthreads();                       // prior round's reads done
        if (threadIdx.x < cnt * 4) {
            const int j = threadIdx.x >> 2, q = threadIdx.x & 3;
            const int t = g_tok[base + ck + j * FX_Z];
            if (q == 0) sT[j] = t;
            sS[j][q] = ((const float4*)g_shrunk)[t * 4 + q];
        }
        __syncthreads();
#pragma unroll 2
        for (int j = 0; j < cnt; j++) {
            const int t = sT[j];
            const float4 s0 = sS[j][0], s1 = sS[j][1];
            const float4 s2 = sS[j][2], s3 = sS[j][3];
            float d0a = s0.x * B0[0].x + s0.y * B0[0].y + s0.z * B0[0].z + s0.w * B0[0].w;
            float d0b = s1.x * B0[1].x + s1.y * B0[1].y + s1.z * B0[1].z + s1.w * B0[1].w;
            float d1a = s0.x * B1[0].x + s0.y * B1[0].y + s0.z * B1[0].z + s0.w * B1[0].w;
            float d1b = s1.x * B1[1].x + s1.y * B1[1].y + s1.z * B1[1].z + s1.w * B1[1].w;
            d0a += s2.x * B0[2].x + s2.y * B0[2].y + s2.z * B0[2].z + s2.w * B0[2].w;
            d0b += s3.x * B0[3].x + s3.y * B0[3].y + s3.z * B0[3].z + s3.w * B0[3].w;
            d1a += s2.x * B1[2].x + s2.y * B1[2].y + s2.z * B1[2].z + s2.w * B1[2].w;
            d1b += s3.x * B1[3].x + s3.y * B1[3].y + s3.z * B1[3].z + s3.w * B1[3].w;
            float2* op = (float2*)(out + (size_t)t * O_DIM + c0);
            float2 cur = *op;
            cur.x += d0a + d0b;
            cur.y += d1a + d1b;
            *op = cur;
        }
    }
}

// ---------------------------------------------------------------------------
// Stream/event resources: LAZY creation on first kernel_launch call.
// Budget: exactly 2 streams (R14 showed 5 streams trips the memory guard);
// events are cheap.
// ---------------------------------------------------------------------------
namespace {
struct ForkJoin {
    cudaStream_t s1 = nullptr, s2 = nullptr;
    cudaEvent_t e0 = nullptr, ecx = nullptr, ew0 = nullptr, ew1 = nullptr,
                eg1 = nullptr;
    bool ok = false;
    ForkJoin() {
        ok = (cudaStreamCreateWithFlags(&s1, cudaStreamNonBlocking) == cudaSuccess) &&
             (cudaStreamCreateWithFlags(&s2, cudaStreamNonBlocking) == cudaSuccess) &&
             (cudaEventCreateWithFlags(&e0, cudaEventDisableTiming) == cudaSuccess) &&
             (cudaEventCreateWithFlags(&ecx, cudaEventDisableTiming) == cudaSuccess) &&
             (cudaEventCreateWithFlags(&ew0, cudaEventDisableTiming) == cudaSuccess) &&
             (cudaEventCreateWithFlags(&ew1, cudaEventDisableTiming) == cudaSuccess) &&
             (cudaEventCreateWithFlags(&eg1, cudaEventDisableTiming) == cudaSuccess);
    }
};
}

// ---------------------------------------------------------------------------
extern "C" void kernel_launch(void* const* d_in, const int* in_sizes, int n_in,
                              void* d_out, int out_size) {
    const float* x      = (const float*)d_in[0];  // (T, H)
    const float* weight = (const float*)d_in[1];  // (O, H)
    const float* bias   = (const float*)d_in[2];  // (O,)
    const float* lora_a = (const float*)d_in[3];  // (L, R, H)
    const float* lora_b = (const float*)d_in[4];  // (L, O, R)
    const int*   rawidx = (const int*)d_in[5];    // (T,) int32 or int64
    float* out = (float*)d_out;                   // (T, O)

    static ForkJoin fj;

    cudaFuncSetAttribute(gemm_hmma, cudaFuncAttributeMaxDynamicSharedMemorySize,
                         DYN_SMEM);

    const int cx_blocks = (T_DIM * H_DIM / 4 + 255) / 256;
    const int cw_half4  = O_DIM * H_DIM / 4 / 2;          // half of W in float4
    const int cw_blocks = cw_half4 / 256;
    const dim3 sh_grid(L_DIM, SH_CH, SH_Z);
    const dim3 fx_grid(L_DIM, O_DIM / 512, FX_Z);
    const dim3 gm_grid(O_DIM / BN / 2, T_DIM / BM);       // (32, 16) per half

    if (fj.ok) {
        // Fork at t=0
        cudaEventRecord(fj.e0, 0);
        cudaStreamWaitEvent(fj.s1, fj.e0, 0);
        cudaStreamWaitEvent(fj.s2, fj.e0, 0);

        // s1: convert_w in 2 halves, event after each
        convert_w<<<cw_blocks, 256, 0, fj.s1>>>(weight, 0);
        cudaEventRecord(fj.ew0, fj.s1);
        convert_w<<<cw_blocks, 256, 0, fj.s1>>>(weight, cw_half4);
        cudaEventRecord(fj.ew1, fj.s1);

        // s2: bucket -> shrink, then gemm half 1 (needs X + W half 1)
        bucket_kernel<<<1, 256, 0, fj.s2>>>(rawidx);
        shrink3<<<sh_grid, 256, 0, fj.s2>>>(x, lora_a);

        // stream 0: convert_x, then gemm half 0
        convert_x<<<cx_blocks, 256>>>(x);
        cudaEventRecord(fj.ecx, 0);
        cudaStreamWaitEvent((cudaStream_t)0, fj.ew0, 0);
        gemm_hmma<<<gm_grid, 256, DYN_SMEM>>>(bias, out, 0);

        // s2: gemm half 1 (concurrent with half 0)
        cudaStreamWaitEvent(fj.s2, fj.ecx, 0);
        cudaStreamWaitEvent(fj.s2, fj.ew1, 0);
        gemm_hmma<<<gm_grid, 256, DYN_SMEM, fj.s2>>>(bias, out, O_DIM / BN / 2);
        cudaEventRecord(fj.eg1, fj.s2);

        // fixup: after gemm half 0 (program order), half 1 + shrink + bucket (eg1)
        cudaStreamWaitEvent((cudaStream_t)0, fj.eg1, 0);
        fixup_kernel<<<fx_grid, 256>>>(lora_b, out);
    } else {
        convert_w<<<cw_blocks, 256>>>(weight, 0);
        convert_w<<<cw_blocks, 256>>>(weight, cw_half4);
        bucket_kernel<<<1, 256>>>(rawidx);
        shrink3<<<sh_grid, 256>>>(x, lora_a);
        convert_x<<<cx_blocks, 256>>>(x);
        gemm_hmma<<<gm_grid, 256, DYN_SMEM>>>(bias, out, 0);
        gemm_hmma<<<gm_grid, 256, DYN_SMEM>>>(bias, out, O_DIM / BN / 2);
        fixup_kernel<<<fx_grid, 256>>>(lora_b, out);
    }
}

// round 16
// speedup vs baseline: 1.0522x; 1.0522x over previous
#include <cuda_runtime.h>
#include <cuda_fp16.h>
#include <cstdint>

#define T_DIM 2048
#define H_DIM 4096
#define O_DIM 4096
#define L_DIM 32
#define R_DIM 16

#define BM 128
#define BN 64
#define BK 32
#define KT_N (H_DIM / BK)          // 128 k-tiles
#define STAGES 4
#define MAT_A_BYTES 8192           // 128 rows x 64 bytes
#define MAT_B_BYTES 4096           // 64 rows x 64 bytes
#define STAGE_BYTES (MAT_A_BYTES + MAT_B_BYTES)   // 12 KB
#define DYN_SMEM (STAGES * STAGE_BYTES)           // 48 KB

#define SH_CH 8                    // shrink H-chunks
#define SH_Z 8                     // shrink token-split
#define CHUNK4 (H_DIM / 4 / SH_CH) // 128 float4 per chunk
#define FX_Z 8                     // fixup token-split
#define FX_CHUNK 32                // staged tokens per round

// ---------------- device scratch ----------------
__device__ int    g_idx32[T_DIM];
__device__ int    g_tok[T_DIM];
__device__ int    g_cnt[L_DIM];
__device__ int    g_base[L_DIM];
__device__ float  g_shrunk[T_DIM * R_DIM];
__device__ __half g_Xhi[T_DIM * H_DIM];
__device__ __half g_Whi[O_DIM * H_DIM];

// ---------------- helpers ----------------
__device__ __forceinline__ uint32_t smem_u32(const void* p) {
    uint32_t a;
    asm("{ .reg .u64 t; cvta.to.shared.u64 t, %1; cvt.u32.u64 %0, t; }"
        : "=r"(a) : "l"(p));
    return a;
}

__device__ __forceinline__ uint32_t swz(uint32_t o) {
    return o ^ ((o >> 3) & 0x30);   // 64B-row swizzle
}

#define CP_ASYNC16(dst, src) \
    asm volatile("cp.async.cg.shared.global [%0], [%1], 16;" :: "r"(dst), "l"(src))
#define CP_COMMIT() asm volatile("cp.async.commit_group;" ::: "memory")
#define CP_WAIT2()  asm volatile("cp.async.wait_group 2;" ::: "memory")

#define LDSM4(d0, d1, d2, d3, a)                                          \
    asm volatile("ldmatrix.sync.aligned.m8n8.x4.shared.b16 {%0,%1,%2,%3}, [%4];" \
                 : "=r"(d0), "=r"(d1), "=r"(d2), "=r"(d3) : "r"(a))

__device__ __forceinline__ void mma16816h(float* c, const uint32_t* a,
                                          uint32_t b0, uint32_t b1) {
    asm volatile(
        "mma.sync.aligned.m16n8k16.row.col.f32.f16.f16.f32 "
        "{%0,%1,%2,%3}, {%4,%5,%6,%7}, {%8,%9}, {%0,%1,%2,%3};"
        : "+f"(c[0]), "+f"(c[1]), "+f"(c[2]), "+f"(c[3])
        : "r"(a[0]), "r"(a[1]), "r"(a[2]), "r"(a[3]), "r"(b0), "r"(b1));
}

// ---------------------------------------------------------------------------
// Kernel 1: index decode (int64 vs int32) + bucket tokens + zero g_shrunk.
// ---------------------------------------------------------------------------
__global__ void bucket_kernel(const int* __restrict__ raw) {
    __shared__ int bad;
    __shared__ int s_cnt[L_DIM];
    __shared__ int s_base[L_DIM];
    const int tid = threadIdx.x;
    if (tid == 0) bad = 0;
    if (tid < L_DIM) s_cnt[tid] = 0;
    __syncthreads();
    {   // 256 pairs = 2048 bytes, in-bounds for either width
        int lo = raw[2 * tid], hi = raw[2 * tid + 1];
        bool ok = (hi == 0 && lo >= 0) || (hi == -1 && lo < 0);
        if (!ok) bad = 1;
    }
    __syncthreads();
    const bool is64 = (bad == 0);
    for (int t = tid; t < T_DIM; t += 256) {
        int v = is64 ? raw[2 * t] : raw[t];
        g_idx32[t] = v;
        if (v >= 0) atomicAdd(&s_cnt[v], 1);
    }
    for (int i = tid; i < T_DIM * R_DIM / 4; i += 256)
        ((float4*)g_shrunk)[i] = make_float4(0, 0, 0, 0);
    __syncthreads();
    if (tid == 0) {
        int a = 0;
        for (int l = 0; l < L_DIM; l++) { s_base[l] = a; a += s_cnt[l]; }
    }
    __syncthreads();
    if (tid < L_DIM) {
        g_cnt[tid] = s_cnt[tid];
        g_base[tid] = s_base[tid];
        s_cnt[tid] = 0;
    }
    __syncthreads();
    for (int t = tid; t < T_DIM; t += 256) {
        int v = g_idx32[t];
        if (v >= 0) {
            int p = atomicAdd(&s_cnt[v], 1);
            g_tok[s_base[v] + p] = t;
        }
    }
}

// ---------------------------------------------------------------------------
// Kernel 2a: fp32 -> fp16 of X
// ---------------------------------------------------------------------------
__global__ void convert_x(const float* __restrict__ src) {
    int i = blockIdx.x * blockDim.x + threadIdx.x;
    if (i >= T_DIM * H_DIM / 4) return;
    float4 v = ((const float4*)src)[i];
    uint2 ph;
    ph.x = ((uint32_t)__half_as_ushort(__float2half(v.y)) << 16) |
           __half_as_ushort(__float2half(v.x));
    ph.y = ((uint32_t)__half_as_ushort(__float2half(v.w)) << 16) |
           __half_as_ushort(__float2half(v.z));
    ((uint2*)g_Xhi)[i] = ph;
}

// ---------------------------------------------------------------------------
// Kernel 2b: fp32 -> fp16 of W, row-chunked (half of W per launch)
// ---------------------------------------------------------------------------
__global__ void convert_w(const float* __restrict__ src, int base4) {
    int i = base4 + blockIdx.x * blockDim.x + threadIdx.x;
    float4 v = ((const float4*)src)[i];
    uint2 ph;
    ph.x = ((uint32_t)__half_as_ushort(__float2half(v.y)) << 16) |
           __half_as_ushort(__float2half(v.x));
    ph.y = ((uint32_t)__half_as_ushort(__float2half(v.w)) << 16) |
           __half_as_ushort(__float2half(v.z));
    ((uint2*)g_Whi)[i] = ph;
}

// ---------------------------------------------------------------------------
// Kernel 3: LoRA shrink, grid (32 adapters, 8 H-chunks, 8 token-slices).
//   Runs CONCURRENTLY with the GEMM (only fixup consumes g_shrunk).
// ---------------------------------------------------------------------------
__global__ __launch_bounds__(256) void shrink3(
    const float* __restrict__ x, const float* __restrict__ lora_a) {
    __shared__ float4 sA4[R_DIM * CHUNK4];       // 16 x 128 float4 = 32 KB
    const int l = blockIdx.x;
    const int n = g_cnt[l];
    if (n == 0) return;
    const int tid = threadIdx.x;
    const int wid = tid >> 5, lid = tid & 31;
    const int slot = blockIdx.z * 8 + wid;       // 0..SH_Z*8-1
    if (blockIdx.z * 8 >= n) return;             // whole block idle -> skip
    const int hb4 = blockIdx.y * CHUNK4;

    const float4* a4 = ((const float4*)lora_a) + (size_t)l * R_DIM * (H_DIM / 4);
    for (int i = tid; i < R_DIM * CHUNK4; i += 256) {
        int r = i / CHUNK4, j4 = i % CHUNK4;
        sA4[i] = a4[r * (H_DIM / 4) + hb4 + j4];
    }
    __syncthreads();

    const int base = g_base[l];
    for (int ti = slot; ti < n; ti += SH_Z * 8) {
        const int t = g_tok[base + ti];
        const float4* x4 = ((const float4*)x) + (size_t)t * (H_DIM / 4) + hb4;
        float4 xv[4];
#pragma unroll
        for (int j = 0; j < 4; j++) xv[j] = x4[lid + 32 * j];
        float acc[R_DIM];
#pragma unroll
        for (int r = 0; r < R_DIM; r++) acc[r] = 0.0f;
#pragma unroll
        for (int j = 0; j < 4; j++) {
#pragma unroll
            for (int r = 0; r < R_DIM; r++) {
                float4 av = sA4[r * CHUNK4 + lid + 32 * j];
                acc[r] += xv[j].x * av.x + xv[j].y * av.y +
                          xv[j].z * av.z + xv[j].w * av.w;
            }
        }
#pragma unroll
        for (int r = 0; r < R_DIM; r++) {
            float v = acc[r];
#pragma unroll
            for (int off = 16; off > 0; off >>= 1)
                v += __shfl_down_sync(0xffffffff, v, off);
            if (lid == 0) atomicAdd(&g_shrunk[t * R_DIM + r], v);
        }
    }
}

// ---------------------------------------------------------------------------
// Kernel 4: fp16 HMMA GEMM (column-range half), epilogue = acc + bias.
//   128x64 tiles, 4-stage cp.async, occ 3. nbase = n-tile offset.
//   Halves run concurrently: half 0 on stream 0, half 1 on s1 (after its W).
// ---------------------------------------------------------------------------
__global__ void __launch_bounds__(256, 3) gemm_hmma(
    const float* __restrict__ bias, float* __restrict__ out, int nbase) {
    extern __shared__ char dynsmem[];
    const uint32_t sbase = smem_u32(dynsmem);
    const int tid = threadIdx.x;
    const int wid = tid >> 5, lid = tid & 31;
    const int m0 = blockIdx.y * BM, n0 = (blockIdx.x + nbase) * BN;
    const int warp_m = wid & 3;        // 0..3 -> 32-row bands
    const int warp_n = wid >> 2;       // 0..1 -> 32-col bands

    const __half* gsrc[3];
    uint32_t sdst[3];
    {
        const __half* baseA = g_Xhi + (size_t)m0 * H_DIM;
        const __half* baseB = g_Whi + (size_t)n0 * H_DIM;
#pragma unroll
        for (int i = 0; i < 3; i++) {
            int c = tid + 256 * i;
            int mat = (c >= 512);
            int w = mat ? (c - 512) : c;
            int row = w >> 2, cq = w & 3;
            gsrc[i] = (mat ? baseB : baseA) + (size_t)row * H_DIM + cq * 8;
            sdst[i] = (mat ? MAT_A_BYTES : 0) + swz((uint32_t)(row * 64 + cq * 16));
        }
    }

#pragma unroll
    for (int s = 0; s < STAGES - 1; s++) {
        uint32_t sb = sbase + s * STAGE_BYTES;
#pragma unroll
        for (int i = 0; i < 3; i++) CP_ASYNC16(sb + sdst[i], gsrc[i] + s * BK);
        CP_COMMIT();
    }

    float acc[2][4][4];
#pragma unroll
    for (int a = 0; a < 2; a++)
#pragma unroll
        for (int b = 0; b < 4; b++)
#pragma unroll
            for (int c = 0; c < 4; c++) acc[a][b][c] = 0.0f;

    const uint32_t a_row = warp_m * 32 + (lid & 15);
    const uint32_t a_kb  = ((lid >> 4) & 1) * 16;
    const uint32_t b_row = warp_n * 32 + ((lid >> 4) & 1) * 8 + (lid & 7);
    const uint32_t b_kb  = ((lid >> 3) & 1) * 16;

#pragma unroll 1
    for (int kt = 0; kt < KT_N; kt++) {
        CP_WAIT2();
        __syncthreads();
        const int nt = kt + STAGES - 1;
        if (nt < KT_N) {
            uint32_t sb = sbase + (nt & 3) * STAGE_BYTES;
#pragma unroll
            for (int i = 0; i < 3; i++) CP_ASYNC16(sb + sdst[i], gsrc[i] + nt * BK);
        }
        CP_COMMIT();

        const uint32_t st = sbase + (kt & 3) * STAGE_BYTES;
#pragma unroll
        for (int kk = 0; kk < 2; kk++) {
            const uint32_t koff = kk * 32;
            uint32_t bh[2][4];
#pragma unroll
            for (int nj2 = 0; nj2 < 2; nj2++) {
                uint32_t o = swz((b_row + nj2 * 16) * 64 + koff + b_kb);
                LDSM4(bh[nj2][0], bh[nj2][1], bh[nj2][2], bh[nj2][3],
                      st + MAT_A_BYTES + o);
            }
#pragma unroll
            for (int mi = 0; mi < 2; mi++) {
                uint32_t ah[4];
                uint32_t o = swz((a_row + mi * 16) * 64 + koff + a_kb);
                LDSM4(ah[0], ah[1], ah[2], ah[3], st + o);
#pragma unroll
                for (int nj = 0; nj < 4; nj++) {
                    const uint32_t b0 = bh[nj >> 1][2 * (nj & 1)];
                    const uint32_t b1 = bh[nj >> 1][2 * (nj & 1) + 1];
                    mma16816h(acc[mi][nj], ah, b0, b1);
                }
            }
        }
    }

    // ---------------- epilogue: + bias only ----------------
    const int l4 = lid >> 2, lq = lid & 3;
    const int colbase = n0 + warp_n * 32 + 2 * lq;
    float2 bia[4];
#pragma unroll
    for (int ni = 0; ni < 4; ni++) {
        bia[ni].x = __ldg(bias + colbase + ni * 8);
        bia[ni].y = __ldg(bias + colbase + ni * 8 + 1);
    }
#pragma unroll
    for (int mi = 0; mi < 2; mi++) {
#pragma unroll
        for (int h = 0; h < 2; h++) {
            const int row = m0 + warp_m * 32 + mi * 16 + h * 8 + l4;
            float* orow = out + (size_t)row * O_DIM;
#pragma unroll
            for (int ni = 0; ni < 4; ni++) {
                const int col = colbase + ni * 8;
                *(float2*)(orow + col) =
                    make_float2(acc[mi][ni][h * 2 + 0] + bia[ni].x,
                                acc[mi][ni][h * 2 + 1] + bia[ni].y);
            }
        }
    }
}

// ---------------------------------------------------------------------------
// Kernel 5: LoRA fixup (post-GEMM): out[t, c] += shrunk[t,:] . B[l, c, :]
// ---------------------------------------------------------------------------
__global__ __launch_bounds__(256) void fixup_kernel(
    const float* __restrict__ lora_b, float* __restrict__ out) {
    __shared__ float4 sS[FX_CHUNK][4];
    __shared__ int    sT[FX_CHUNK];
    const int l = blockIdx.x;
    const int n = g_cnt[l];
    const int z = blockIdx.z;
    if (z >= n) return;
    const int c0 = blockIdx.y * 512 + threadIdx.x * 2;

    const float4* b0 = (const float4*)(lora_b + ((size_t)l * O_DIM + c0) * R_DIM);
    const float4* b1 = (const float4*)(lora_b + ((size_t)l * O_DIM + c0 + 1) * R_DIM);
    float4 B0[4], B1[4];
#pragma unroll
    for (int q = 0; q < 4; q++) { B0[q] = b0[q]; B1[q] = b1[q]; }

    const int base = g_base[l];
    for (int ck = z; ck < n; ck += FX_Z * FX_CHUNK) {
        int cnt = (n - ck + FX_Z - 1) / FX_Z;
        if (cnt > FX_CHUNK) cnt = FX_CHUNK;
        __syncthreads();                       // prior round's reads done
        if (threadIdx.x < cnt * 4) {
            const int j = threadIdx.x >> 2, q = threadIdx.x & 3;
            const int t = g_tok[base + ck + j * FX_Z];
            if (q == 0) sT[j] = t;
            sS[j][q] = ((const float4*)g_shrunk)[t * 4 + q];
        }
        __syncthreads();
#pragma unroll 2
        for (int j = 0; j < cnt; j++) {
            const int t = sT[j];
            const float4 s0 = sS[j][0], s1 = sS[j][1];
            const float4 s2 = sS[j][2], s3 = sS[j][3];
            float d0a = s0.x * B0[0].x + s0.y * B0[0].y + s0.z * B0[0].z + s0.w * B0[0].w;
            float d0b = s1.x * B0[1].x + s1.y * B0[1].y + s1.z * B0[1].z + s1.w * B0[1].w;
            float d1a = s0.x * B1[0].x + s0.y * B1[0].y + s0.z * B1[0].z + s0.w * B1[0].w;
            float d1b = s1.x * B1[1].x + s1.y * B1[1].y + s1.z * B1[1].z + s1.w * B1[1].w;
            d0a += s2.x * B0[2].x + s2.y * B0[2].y + s2.z * B0[2].z + s2.w * B0[2].w;
            d0b += s3.x * B0[3].x + s3.y * B0[3].y + s3.z * B0[3].z + s3.w * B0[3].w;
            d1a += s2.x * B1[2].x + s2.y * B1[2].y + s2.z * B1[2].z + s2.w * B1[2].w;
            d1b += s3.x * B1[3].x + s3.y * B1[3].y + s3.z * B1[3].z + s3.w * B1[3].w;
            float2* op = (float2*)(out + (size_t)t * O_DIM + c0);
            float2 cur = *op;
            cur.x += d0a + d0b;
            cur.y += d1a + d1b;
            *op = cur;
        }
    }
}

// ---------------------------------------------------------------------------
// Stream/event resources: LAZY creation on first kernel_launch call.
// Budget: exactly 2 streams (5 streams tripped the memory guard in R14).
// ---------------------------------------------------------------------------
namespace {
struct ForkJoin {
    cudaStream_t s1 = nullptr, s2 = nullptr;
    cudaEvent_t e0 = nullptr, ecx = nullptr, ew0 = nullptr, e2 = nullptr,
                eg1 = nullptr;
    bool ok = false;
    ForkJoin() {
        ok = (cudaStreamCreateWithFlags(&s1, cudaStreamNonBlocking) == cudaSuccess) &&
             (cudaStreamCreateWithFlags(&s2, cudaStreamNonBlocking) == cudaSuccess) &&
             (cudaEventCreateWithFlags(&e0, cudaEventDisableTiming) == cudaSuccess) &&
             (cudaEventCreateWithFlags(&ecx, cudaEventDisableTiming) == cudaSuccess) &&
             (cudaEventCreateWithFlags(&ew0, cudaEventDisableTiming) == cudaSuccess) &&
             (cudaEventCreateWithFlags(&e2, cudaEventDisableTiming) == cudaSuccess) &&
             (cudaEventCreateWithFlags(&eg1, cudaEventDisableTiming) == cudaSuccess);
    }
};
}

// ---------------------------------------------------------------------------
extern "C" void kernel_launch(void* const* d_in, const int* in_sizes, int n_in,
                              void* d_out, int out_size) {
    const float* x      = (const float*)d_in[0];  // (T, H)
    const float* weight = (const float*)d_in[1];  // (O, H)
    const float* bias   = (const float*)d_in[2];  // (O,)
    const float* lora_a = (const float*)d_in[3];  // (L, R, H)
    const float* lora_b = (const float*)d_in[4];  // (L, O, R)
    const int*   rawidx = (const int*)d_in[5];    // (T,) int32 or int64
    float* out = (float*)d_out;                   // (T, O)

    static ForkJoin fj;

    cudaFuncSetAttribute(gemm_hmma, cudaFuncAttributeMaxDynamicSharedMemorySize,
                         DYN_SMEM);

    const int cx_blocks = (T_DIM * H_DIM / 4 + 255) / 256;
    const int cw_half4  = O_DIM * H_DIM / 4 / 2;          // half of W in float4
    const int cw_blocks = cw_half4 / 256;
    const dim3 sh_grid(L_DIM, SH_CH, SH_Z);
    const dim3 fx_grid(L_DIM, O_DIM / 512, FX_Z);
    const dim3 gm_grid(O_DIM / BN / 2, T_DIM / BM);       // (32, 16) per half

    if (fj.ok) {
        // Fork at t=0
        cudaEventRecord(fj.e0, 0);
        cudaStreamWaitEvent(fj.s1, fj.e0, 0);
        cudaStreamWaitEvent(fj.s2, fj.e0, 0);

        // s2: bucket -> shrink (pure overlap; never gates any GEMM)
        bucket_kernel<<<1, 256, 0, fj.s2>>>(rawidx);
        shrink3<<<sh_grid, 256, 0, fj.s2>>>(x, lora_a);
        cudaEventRecord(fj.e2, fj.s2);

        // s1: convert_w half 0 -> ew0 -> half 1 -> (wait ecx) -> gemm half 1
        convert_w<<<cw_blocks, 256, 0, fj.s1>>>(weight, 0);
        cudaEventRecord(fj.ew0, fj.s1);
        convert_w<<<cw_blocks, 256, 0, fj.s1>>>(weight, cw_half4);

        // stream 0: convert_x -> ecx -> (wait ew0) -> gemm half 0
        convert_x<<<cx_blocks, 256>>>(x);
        cudaEventRecord(fj.ecx, 0);
        cudaStreamWaitEvent((cudaStream_t)0, fj.ew0, 0);
        gemm_hmma<<<gm_grid, 256, DYN_SMEM>>>(bias, out, 0);

        // s1: gemm half 1 (after convert_w half 1 by stream order, + X ready)
        cudaStreamWaitEvent(fj.s1, fj.ecx, 0);
        gemm_hmma<<<gm_grid, 256, DYN_SMEM, fj.s1>>>(bias, out, O_DIM / BN / 2);
        cudaEventRecord(fj.eg1, fj.s1);

        // fixup: after gemm half 0 (program order) + half 1 + shrink
        cudaStreamWaitEvent((cudaStream_t)0, fj.eg1, 0);
        cudaStreamWaitEvent((cudaStream_t)0, fj.e2, 0);
        fixup_kernel<<<fx_grid, 256>>>(lora_b, out);
    } else {
        convert_w<<<cw_blocks, 256>>>(weight, 0);
        convert_w<<<cw_blocks, 256>>>(weight, cw_half4);
        bucket_kernel<<<1, 256>>>(rawidx);
        shrink3<<<sh_grid, 256>>>(x, lora_a);
        convert_x<<<cx_blocks, 256>>>(x);
        gemm_hmma<<<gm_grid, 256, DYN_SMEM>>>(bias, out, 0);
        gemm_hmma<<<gm_grid, 256, DYN_SMEM>>>(bias, out, O_DIM / BN / 2);
        fixup_kernel<<<fx_grid, 256>>>(lora_b, out);
    }
}

// round 17
// speedup vs baseline: 1.0996x; 1.0451x over previous
#include <cuda_runtime.h>
#include <cuda_fp16.h>
#include <cstdint>

#define T_DIM 2048
#define H_DIM 4096
#define O_DIM 4096
#define L_DIM 32
#define R_DIM 16

#define BM 128
#define BN 64
#define BK 32
#define KT_N (H_DIM / BK)          // 128 k-tiles
#define STAGES 4
#define MAT_A_BYTES 8192           // 128 rows x 64 bytes
#define MAT_B_BYTES 4096           // 64 rows x 64 bytes
#define STAGE_BYTES (MAT_A_BYTES + MAT_B_BYTES)   // 12 KB
#define DYN_SMEM (STAGES * STAGE_BYTES)           // 48 KB

#define SH_CH 8                    // shrink H-chunks
#define SH_Z 8                     // shrink token-split
#define CHUNK4 (H_DIM / 4 / SH_CH) // 128 float4 per chunk
#define FX_Z 8                     // fixup token-split
#define FX_CHUNK 32                // staged tokens per round

// ---------------- device scratch ----------------
__device__ int    g_idx32[T_DIM];
__device__ int    g_tok[T_DIM];
__device__ int    g_cnt[L_DIM];
__device__ int    g_base[L_DIM];
__device__ float  g_shrunk[T_DIM * R_DIM];
__device__ __half g_Xhi[T_DIM * H_DIM];
__device__ __half g_Whi[O_DIM * H_DIM];

// ---------------- helpers ----------------
__device__ __forceinline__ uint32_t smem_u32(const void* p) {
    uint32_t a;
    asm("{ .reg .u64 t; cvta.to.shared.u64 t, %1; cvt.u32.u64 %0, t; }"
        : "=r"(a) : "l"(p));
    return a;
}

__device__ __forceinline__ uint32_t swz(uint32_t o) {
    return o ^ ((o >> 3) & 0x30);   // 64B-row swizzle
}

#define CP_ASYNC16(dst, src) \
    asm volatile("cp.async.cg.shared.global [%0], [%1], 16;" :: "r"(dst), "l"(src))
#define CP_COMMIT() asm volatile("cp.async.commit_group;" ::: "memory")
#define CP_WAIT2()  asm volatile("cp.async.wait_group 2;" ::: "memory")

#define LDSM4(d0, d1, d2, d3, a)                                          \
    asm volatile("ldmatrix.sync.aligned.m8n8.x4.shared.b16 {%0,%1,%2,%3}, [%4];" \
                 : "=r"(d0), "=r"(d1), "=r"(d2), "=r"(d3) : "r"(a))

__device__ __forceinline__ void mma16816h(float* c, const uint32_t* a,
                                          uint32_t b0, uint32_t b1) {
    asm volatile(
        "mma.sync.aligned.m16n8k16.row.col.f32.f16.f16.f32 "
        "{%0,%1,%2,%3}, {%4,%5,%6,%7}, {%8,%9}, {%0,%1,%2,%3};"
        : "+f"(c[0]), "+f"(c[1]), "+f"(c[2]), "+f"(c[3])
        : "r"(a[0]), "r"(a[1]), "r"(a[2]), "r"(a[3]), "r"(b0), "r"(b1));
}

__device__ __forceinline__ uint2 pack_half4(float4 v) {
    uint2 ph;
    ph.x = ((uint32_t)__half_as_ushort(__float2half(v.y)) << 16) |
           __half_as_ushort(__float2half(v.x));
    ph.y = ((uint32_t)__half_as_ushort(__float2half(v.w)) << 16) |
           __half_as_ushort(__float2half(v.z));
    return ph;
}

// ---------------------------------------------------------------------------
// Kernel 1: index decode (int64 vs int32) + bucket tokens + zero g_shrunk.
// ---------------------------------------------------------------------------
__global__ void bucket_kernel(const int* __restrict__ raw) {
    __shared__ int bad;
    __shared__ int s_cnt[L_DIM];
    __shared__ int s_base[L_DIM];
    const int tid = threadIdx.x;
    if (tid == 0) bad = 0;
    if (tid < L_DIM) s_cnt[tid] = 0;
    __syncthreads();
    {   // 256 pairs = 2048 bytes, in-bounds for either width
        int lo = raw[2 * tid], hi = raw[2 * tid + 1];
        bool ok = (hi == 0 && lo >= 0) || (hi == -1 && lo < 0);
        if (!ok) bad = 1;
    }
    __syncthreads();
    const bool is64 = (bad == 0);
    for (int t = tid; t < T_DIM; t += 256) {
        int v = is64 ? raw[2 * t] : raw[t];
        g_idx32[t] = v;
        if (v >= 0) atomicAdd(&s_cnt[v], 1);
    }
    for (int i = tid; i < T_DIM * R_DIM / 4; i += 256)
        ((float4*)g_shrunk)[i] = make_float4(0, 0, 0, 0);
    __syncthreads();
    if (tid == 0) {
        int a = 0;
        for (int l = 0; l < L_DIM; l++) { s_base[l] = a; a += s_cnt[l]; }
    }
    __syncthreads();
    if (tid < L_DIM) {
        g_cnt[tid] = s_cnt[tid];
        g_base[tid] = s_base[tid];
        s_cnt[tid] = 0;
    }
    __syncthreads();
    for (int t = tid; t < T_DIM; t += 256) {
        int v = g_idx32[t];
        if (v >= 0) {
            int p = atomicAdd(&s_cnt[v], 1);
            g_tok[s_base[v] + p] = t;
        }
    }
}

// ---------------------------------------------------------------------------
// Kernel 2a: fp32 -> fp16 of X, 2 float4 per thread (MLP 2)
// ---------------------------------------------------------------------------
__global__ void convert_x(const float* __restrict__ src) {
    int i0 = blockIdx.x * 512 + threadIdx.x;
    int i1 = i0 + 256;
    float4 v0 = ((const float4*)src)[i0];
    float4 v1 = ((const float4*)src)[i1];
    ((uint2*)g_Xhi)[i0] = pack_half4(v0);
    ((uint2*)g_Xhi)[i1] = pack_half4(v1);
}

// ---------------------------------------------------------------------------
// Kernel 2b: fp32 -> fp16 of W, 2 float4 per thread (MLP 2)
// ---------------------------------------------------------------------------
__global__ void convert_w(const float* __restrict__ src) {
    int i0 = blockIdx.x * 512 + threadIdx.x;
    int i1 = i0 + 256;
    float4 v0 = ((const float4*)src)[i0];
    float4 v1 = ((const float4*)src)[i1];
    ((uint2*)g_Whi)[i0] = pack_half4(v0);
    ((uint2*)g_Whi)[i1] = pack_half4(v1);
}

// ---------------------------------------------------------------------------
// Kernel 3: LoRA shrink, grid (32 adapters, 8 H-chunks, 8 token-slices).
//   Runs on the side stream; finishes around the time the GEMM starts.
// ---------------------------------------------------------------------------
__global__ __launch_bounds__(256) void shrink3(
    const float* __restrict__ x, const float* __restrict__ lora_a) {
    __shared__ float4 sA4[R_DIM * CHUNK4];       // 16 x 128 float4 = 32 KB
    const int l = blockIdx.x;
    const int n = g_cnt[l];
    if (n == 0) return;
    const int tid = threadIdx.x;
    const int wid = tid >> 5, lid = tid & 31;
    const int slot = blockIdx.z * 8 + wid;       // 0..SH_Z*8-1
    if (blockIdx.z * 8 >= n) return;             // whole block idle -> skip
    const int hb4 = blockIdx.y * CHUNK4;

    const float4* a4 = ((const float4*)lora_a) + (size_t)l * R_DIM * (H_DIM / 4);
    for (int i = tid; i < R_DIM * CHUNK4; i += 256) {
        int r = i / CHUNK4, j4 = i % CHUNK4;
        sA4[i] = a4[r * (H_DIM / 4) + hb4 + j4];
    }
    __syncthreads();

    const int base = g_base[l];
    for (int ti = slot; ti < n; ti += SH_Z * 8) {
        const int t = g_tok[base + ti];
        const float4* x4 = ((const float4*)x) + (size_t)t * (H_DIM / 4) + hb4;
        float4 xv[4];
#pragma unroll
        for (int j = 0; j < 4; j++) xv[j] = x4[lid + 32 * j];
        float acc[R_DIM];
#pragma unroll
        for (int r = 0; r < R_DIM; r++) acc[r] = 0.0f;
#pragma unroll
        for (int j = 0; j < 4; j++) {
#pragma unroll
            for (int r = 0; r < R_DIM; r++) {
                float4 av = sA4[r * CHUNK4 + lid + 32 * j];
                acc[r] += xv[j].x * av.x + xv[j].y * av.y +
                          xv[j].z * av.z + xv[j].w * av.w;
            }
        }
#pragma unroll
        for (int r = 0; r < R_DIM; r++) {
            float v = acc[r];
#pragma unroll
            for (int off = 16; off > 0; off >>= 1)
                v += __shfl_down_sync(0xffffffff, v, off);
            if (lid == 0) atomicAdd(&g_shrunk[t * R_DIM + r], v);
        }
    }
}

// ---------------------------------------------------------------------------
// Kernel 4: fp16 HMMA GEMM (monolithic), epilogue = acc + bias.
//   128x64 tiles (1024 tiles -> 98.8% SM packing), 4-stage cp.async, occ 3.
// ---------------------------------------------------------------------------
__global__ void __launch_bounds__(256, 3) gemm_hmma(
    const float* __restrict__ bias, float* __restrict__ out) {
    extern __shared__ char dynsmem[];
    const uint32_t sbase = smem_u32(dynsmem);
    const int tid = threadIdx.x;
    const int wid = tid >> 5, lid = tid & 31;
    const int m0 = blockIdx.y * BM, n0 = blockIdx.x * BN;
    const int warp_m = wid & 3;        // 0..3 -> 32-row bands
    const int warp_n = wid >> 2;       // 0..1 -> 32-col bands

    const __half* gsrc[3];
    uint32_t sdst[3];
    {
        const __half* baseA = g_Xhi + (size_t)m0 * H_DIM;
        const __half* baseB = g_Whi + (size_t)n0 * H_DIM;
#pragma unroll
        for (int i = 0; i < 3; i++) {
            int c = tid + 256 * i;
            int mat = (c >= 512);
            int w = mat ? (c - 512) : c;
            int row = w >> 2, cq = w & 3;
            gsrc[i] = (mat ? baseB : baseA) + (size_t)row * H_DIM + cq * 8;
            sdst[i] = (mat ? MAT_A_BYTES : 0) + swz((uint32_t)(row * 64 + cq * 16));
        }
    }

#pragma unroll
    for (int s = 0; s < STAGES - 1; s++) {
        uint32_t sb = sbase + s * STAGE_BYTES;
#pragma unroll
        for (int i = 0; i < 3; i++) CP_ASYNC16(sb + sdst[i], gsrc[i] + s * BK);
        CP_COMMIT();
    }

    float acc[2][4][4];
#pragma unroll
    for (int a = 0; a < 2; a++)
#pragma unroll
        for (int b = 0; b < 4; b++)
#pragma unroll
            for (int c = 0; c < 4; c++) acc[a][b][c] = 0.0f;

    const uint32_t a_row = warp_m * 32 + (lid & 15);
    const uint32_t a_kb  = ((lid >> 4) & 1) * 16;
    const uint32_t b_row = warp_n * 32 + ((lid >> 4) & 1) * 8 + (lid & 7);
    const uint32_t b_kb  = ((lid >> 3) & 1) * 16;

#pragma unroll 1
    for (int kt = 0; kt < KT_N; kt++) {
        CP_WAIT2();
        __syncthreads();
        const int nt = kt + STAGES - 1;
        if (nt < KT_N) {
            uint32_t sb = sbase + (nt & 3) * STAGE_BYTES;
#pragma unroll
            for (int i = 0; i < 3; i++) CP_ASYNC16(sb + sdst[i], gsrc[i] + nt * BK);
        }
        CP_COMMIT();

        const uint32_t st = sbase + (kt & 3) * STAGE_BYTES;
#pragma unroll
        for (int kk = 0; kk < 2; kk++) {
            const uint32_t koff = kk * 32;
            uint32_t bh[2][4];
#pragma unroll
            for (int nj2 = 0; nj2 < 2; nj2++) {
                uint32_t o = swz((b_row + nj2 * 16) * 64 + koff + b_kb);
                LDSM4(bh[nj2][0], bh[nj2][1], bh[nj2][2], bh[nj2][3],
                      st + MAT_A_BYTES + o);
            }
#pragma unroll
            for (int mi = 0; mi < 2; mi++) {
                uint32_t ah[4];
                uint32_t o = swz((a_row + mi * 16) * 64 + koff + a_kb);
                LDSM4(ah[0], ah[1], ah[2], ah[3], st + o);
#pragma unroll
                for (int nj = 0; nj < 4; nj++) {
                    const uint32_t b0 = bh[nj >> 1][2 * (nj & 1)];
                    const uint32_t b1 = bh[nj >> 1][2 * (nj & 1) + 1];
                    mma16816h(acc[mi][nj], ah, b0, b1);
                }
            }
        }
    }

    // ---------------- epilogue: + bias only ----------------
    const int l4 = lid >> 2, lq = lid & 3;
    const int colbase = n0 + warp_n * 32 + 2 * lq;
    float2 bia[4];
#pragma unroll
    for (int ni = 0; ni < 4; ni++) {
        bia[ni].x = __ldg(bias + colbase + ni * 8);
        bia[ni].y = __ldg(bias + colbase + ni * 8 + 1);
    }
#pragma unroll
    for (int mi = 0; mi < 2; mi++) {
#pragma unroll
        for (int h = 0; h < 2; h++) {
            const int row = m0 + warp_m * 32 + mi * 16 + h * 8 + l4;
            float* orow = out + (size_t)row * O_DIM;
#pragma unroll
            for (int ni = 0; ni < 4; ni++) {
                const int col = colbase + ni * 8;
                *(float2*)(orow + col) =
                    make_float2(acc[mi][ni][h * 2 + 0] + bia[ni].x,
                                acc[mi][ni][h * 2 + 1] + bia[ni].y);
            }
        }
    }
}

// ---------------------------------------------------------------------------
// Kernel 5: LoRA fixup (post-GEMM): out[t, c] += shrunk[t,:] . B[l, c, :]
// ---------------------------------------------------------------------------
__global__ __launch_bounds__(256) void fixup_kernel(
    const float* __restrict__ lora_b, float* __restrict__ out) {
    __shared__ float4 sS[FX_CHUNK][4];
    __shared__ int    sT[FX_CHUNK];
    const int l = blockIdx.x;
    const int n = g_cnt[l];
    const int z = blockIdx.z;
    if (z >= n) return;
    const int c0 = blockIdx.y * 512 + threadIdx.x * 2;

    const float4* b0 = (const float4*)(lora_b + ((size_t)l * O_DIM + c0) * R_DIM);
    const float4* b1 = (const float4*)(lora_b + ((size_t)l * O_DIM + c0 + 1) * R_DIM);
    float4 B0[4], B1[4];
#pragma unroll
    for (int q = 0; q < 4; q++) { B0[q] = b0[q]; B1[q] = b1[q]; }

    const int base = g_base[l];
    for (int ck = z; ck < n; ck += FX_Z * FX_CHUNK) {
        int cnt = (n - ck + FX_Z - 1) / FX_Z;
        if (cnt > FX_CHUNK) cnt = FX_CHUNK;
        __syncthreads();                       // prior round's reads done
        if (threadIdx.x < cnt * 4) {
            const int j = threadIdx.x >> 2, q = threadIdx.x & 3;
            const int t = g_tok[base + ck + j * FX_Z];
            if (q == 0) sT[j] = t;
            sS[j][q] = ((const float4*)g_shrunk)[t * 4 + q];
        }
        __syncthreads();
#pragma unroll 2
        for (int j = 0; j < cnt; j++) {
            const int t = sT[j];
            const float4 s0 = sS[j][0], s1 = sS[j][1];
            const float4 s2 = sS[j][2], s3 = sS[j][3];
            float d0a = s0.x * B0[0].x + s0.y * B0[0].y + s0.z * B0[0].z + s0.w * B0[0].w;
            float d0b = s1.x * B0[1].x + s1.y * B0[1].y + s1.z * B0[1].z + s1.w * B0[1].w;
            float d1a = s0.x * B1[0].x + s0.y * B1[0].y + s0.z * B1[0].z + s0.w * B1[0].w;
            float d1b = s1.x * B1[1].x + s1.y * B1[1].y + s1.z * B1[1].z + s1.w * B1[1].w;
            d0a += s2.x * B0[2].x + s2.y * B0[2].y + s2.z * B0[2].z + s2.w * B0[2].w;
            d0b += s3.x * B0[3].x + s3.y * B0[3].y + s3.z * B0[3].z + s3.w * B0[3].w;
            d1a += s2.x * B1[2].x + s2.y * B1[2].y + s2.z * B1[2].z + s2.w * B1[2].w;
            d1b += s3.x * B1[3].x + s3.y * B1[3].y + s3.z * B1[3].z + s3.w * B1[3].w;
            float2* op = (float2*)(out + (size_t)t * O_DIM + c0);
            float2 cur = *op;
            cur.x += d0a + d0b;
            cur.y += d1a + d1b;
            *op = cur;
        }
    }
}

// ---------------------------------------------------------------------------
// Stream/event resources: LAZY creation on first kernel_launch call.
// Budget: exactly 2 streams (5 streams tripped the memory guard in R14).
// ---------------------------------------------------------------------------
namespace {
struct ForkJoin {
    cudaStream_t s1 = nullptr, s2 = nullptr;
    cudaEvent_t e0 = nullptr, e1 = nullptr, e2 = nullptr;
    bool ok = false;
    ForkJoin() {
        ok = (cudaStreamCreateWithFlags(&s1, cudaStreamNonBlocking) == cudaSuccess) &&
             (cudaStreamCreateWithFlags(&s2, cudaStreamNonBlocking) == cudaSuccess) &&
             (cudaEventCreateWithFlags(&e0, cudaEventDisableTiming) == cudaSuccess) &&
             (cudaEventCreateWithFlags(&e1, cudaEventDisableTiming) == cudaSuccess) &&
             (cudaEventCreateWithFlags(&e2, cudaEventDisableTiming) == cudaSuccess);
    }
};
}

// ---------------------------------------------------------------------------
extern "C" void kernel_launch(void* const* d_in, const int* in_sizes, int n_in,
                              void* d_out, int out_size) {
    const float* x      = (const float*)d_in[0];  // (T, H)
    const float* weight = (const float*)d_in[1];  // (O, H)
    const float* bias   = (const float*)d_in[2];  // (O,)
    const float* lora_a = (const float*)d_in[3];  // (L, R, H)
    const float* lora_b = (const float*)d_in[4];  // (L, O, R)
    const int*   rawidx = (const int*)d_in[5];    // (T,) int32 or int64
    float* out = (float*)d_out;                   // (T, O)

    static ForkJoin fj;

    cudaFuncSetAttribute(gemm_hmma, cudaFuncAttributeMaxDynamicSharedMemorySize,
                         DYN_SMEM);

    const int cx_blocks = T_DIM * H_DIM / 4 / 512;        // 2 float4 / thread
    const int cw_blocks = O_DIM * H_DIM / 4 / 512;
    const dim3 sh_grid(L_DIM, SH_CH, SH_Z);
    const dim3 fx_grid(L_DIM, O_DIM / 512, FX_Z);
    const dim3 gm_grid(O_DIM / BN, T_DIM / BM);           // (64, 16) = 1024 tiles

    if (fj.ok) {
        // Fork at t=0: convert_w on s1, bucket->shrink on s2, convert_x on 0.
        cudaEventRecord(fj.e0, 0);
        cudaStreamWaitEvent(fj.s1, fj.e0, 0);
        cudaStreamWaitEvent(fj.s2, fj.e0, 0);

        convert_w<<<cw_blocks, 256, 0, fj.s1>>>(weight);
        cudaEventRecord(fj.e1, fj.s1);

        bucket_kernel<<<1, 256, 0, fj.s2>>>(rawidx);
        shrink3<<<sh_grid, 256, 0, fj.s2>>>(x, lora_a);   // overlaps the GEMM head
        cudaEventRecord(fj.e2, fj.s2);

        convert_x<<<cx_blocks, 256>>>(x);

        // GEMM waits only on converts
        cudaStreamWaitEvent((cudaStream_t)0, fj.e1, 0);
        gemm_hmma<<<gm_grid, 256, DYN_SMEM>>>(bias, out);

        // fixup waits on GEMM (program order) + shrink (event)
        cudaStreamWaitEvent((cudaStream_t)0, fj.e2, 0);
        fixup_kernel<<<fx_grid, 256>>>(lora_b, out);
    } else {
        convert_w<<<cw_blocks, 256>>>(weight);
        bucket_kernel<<<1, 256>>>(rawidx);
        shrink3<<<sh_grid, 256>>>(x, lora_a);
        convert_x<<<cx_blocks, 256>>>(x);
        gemm_hmma<<<gm_grid, 256, DYN_SMEM>>>(bias, out);
        fixup_kernel<<<fx_grid, 256>>>(lora_b, out);
    }
}